// round 3
// baseline (speedup 1.0000x reference)
#include <cuda_runtime.h>

#define NMAX 100000
#define HH   128

// Scratch: per-node projections. Layout [node][256]:
//   cols   0..127 : z @ W1a  (node used as FIRST/concat-left endpoint)
//   cols 128..255 : z @ W1b  (node used as SECOND/concat-right endpoint)
__device__ float g_P[(size_t)NMAX * 256];  // projections of z_pnode
__device__ float g_O[(size_t)NMAX * 256];  // projections of z_onode

// C[n,256] = A[n,128] @ B[128,256], where B = [w1[0:128,:] | w1[128:256,:]].
// Tile: 64 rows x 64 cols per block, K=128 loaded entirely into smem once.
// 256 threads, each computes a 4x4 microtile.
__global__ __launch_bounds__(256, 3)
void gemm256_kernel(const float* __restrict__ A, const float* __restrict__ w1,
                    int n, int which) {
    __shared__ float As[128][64];   // As[k][r] = A[rowBase+r][k]
    __shared__ float Bs[128][64];   // Bs[k][j] = B[k][jb+j]

    float* Cg = which ? g_O : g_P;
    const int tid = threadIdx.x;
    const int rowBase = blockIdx.x * 64;
    const int jb = blockIdx.y * 64;

    // ---- Load A tile (transposed into smem, conflict-free STS) ----
    #pragma unroll
    for (int it = 0; it < 8; it++) {
        int li = tid + it * 256;        // 0..2047 float4 slots
        int r  = li & 63;               // row within tile
        int k4 = (li >> 6) * 4;         // k offset (0..124)
        float4 v = make_float4(0.f, 0.f, 0.f, 0.f);
        int row = rowBase + r;
        if (row < n)
            v = *reinterpret_cast<const float4*>(A + (size_t)row * HH + k4);
        As[k4 + 0][r] = v.x;
        As[k4 + 1][r] = v.y;
        As[k4 + 2][r] = v.z;
        As[k4 + 3][r] = v.w;
    }

    // ---- Load B tile. Column blocks never straddle the W1a/W1b boundary. ----
    const float* Bsrc = (jb < 128) ? (w1 + jb)
                                   : (w1 + 128 * 128 + (jb - 128));
    #pragma unroll
    for (int it = 0; it < 8; it++) {
        int li = tid + it * 256;        // 0..2047
        int k  = li >> 4;               // 0..127
        int j4 = (li & 15) * 4;         // 0..60
        *reinterpret_cast<float4*>(&Bs[k][j4]) =
            *reinterpret_cast<const float4*>(Bsrc + k * 128 + j4);
    }
    __syncthreads();

    const int tx = tid & 15;            // col group
    const int ty = tid >> 4;            // row group
    float acc[4][4];
    #pragma unroll
    for (int i = 0; i < 4; i++)
        #pragma unroll
        for (int j = 0; j < 4; j++)
            acc[i][j] = 0.f;

    #pragma unroll 16
    for (int k = 0; k < 128; k++) {
        float4 a = *reinterpret_cast<const float4*>(&As[k][ty * 4]);
        float4 b = *reinterpret_cast<const float4*>(&Bs[k][tx * 4]);
        float av[4] = {a.x, a.y, a.z, a.w};
        float bv[4] = {b.x, b.y, b.z, b.w};
        #pragma unroll
        for (int i = 0; i < 4; i++)
            #pragma unroll
            for (int j = 0; j < 4; j++)
                acc[i][j] = fmaf(av[i], bv[j], acc[i][j]);
    }

    #pragma unroll
    for (int i = 0; i < 4; i++) {
        int row = rowBase + ty * 4 + i;
        if (row < n) {
            float4 v = make_float4(acc[i][0], acc[i][1], acc[i][2], acc[i][3]);
            *reinterpret_cast<float4*>(Cg + (size_t)row * 256 + jb + tx * 4) = v;
        }
    }
}

// One warp per edge: gather X[src] (left projection) and Y[dst] (right
// projection), apply bias + relu, dot with w2, warp-reduce, write scalar.
__global__ __launch_bounds__(256)
void edge_kernel(int xsel, int xoff, int ysel, int yoff,
                 const int* __restrict__ idx,
                 const float* __restrict__ b1,
                 const float* __restrict__ w2,
                 const float* __restrict__ b2,
                 float* __restrict__ out, int E) {
    const float* X = (xsel ? g_O : g_P) + xoff;
    const float* Y = (ysel ? g_O : g_P) + yoff;

    const int lane = threadIdx.x & 31;
    const int l4 = lane * 4;
    unsigned gw = (blockIdx.x * blockDim.x + threadIdx.x) >> 5;
    unsigned nw = (gridDim.x * blockDim.x) >> 5;

    float4 b1v = *reinterpret_cast<const float4*>(b1 + l4);
    float4 w2v = *reinterpret_cast<const float4*>(w2 + l4);
    float b2v = __ldg(b2);

    for (unsigned e = gw; e < (unsigned)E; e += nw) {
        int s = idx[e];
        int d = idx[E + e];
        float4 x = *reinterpret_cast<const float4*>(X + (size_t)s * 256 + l4);
        float4 y = *reinterpret_cast<const float4*>(Y + (size_t)d * 256 + l4);

        float t, sum;
        t = x.x + y.x + b1v.x; sum  = fmaxf(t, 0.f) * w2v.x;
        t = x.y + y.y + b1v.y; sum += fmaxf(t, 0.f) * w2v.y;
        t = x.z + y.z + b1v.z; sum += fmaxf(t, 0.f) * w2v.z;
        t = x.w + y.w + b1v.w; sum += fmaxf(t, 0.f) * w2v.w;

        #pragma unroll
        for (int o = 16; o > 0; o >>= 1)
            sum += __shfl_xor_sync(0xffffffffu, sum, o);

        if (lane == 0)
            out[e] = sum + b2v;
    }
}

extern "C" void kernel_launch(void* const* d_in, const int* in_sizes, int n_in,
                              void* d_out, int out_size) {
    const float* z_p = (const float*)d_in[0];
    const float* z_o = (const float*)d_in[1];
    const int*   e1  = (const int*)d_in[2];   // ptnp: pnode src, onode dst
    const int*   e2  = (const int*)d_in[3];   // nptp: onode src, pnode dst
    const int*   e3  = (const int*)d_in[4];   // nptnp: onode src, onode dst
    const float* w1  = (const float*)d_in[5];
    const float* b1  = (const float*)d_in[6];
    const float* w2  = (const float*)d_in[7];
    const float* b2  = (const float*)d_in[8];
    float* out = (float*)d_out;

    const int n = in_sizes[0] / HH;       // 100000
    const int E = in_sizes[2] / 2;        // 500000
    (void)n_in; (void)out_size;

    dim3 g((n + 63) / 64, 4);
    gemm256_kernel<<<g, 256>>>(z_p, w1, n, 0);
    gemm256_kernel<<<g, 256>>>(z_o, w1, n, 1);

    // 8 warps per 256-thread block -> ~1 edge per warp
    int blocks = (E + 7) / 8;
    // ptnp:  left = P_a (g_P + 0),   right = O_b (g_O + 128)
    edge_kernel<<<blocks, 256>>>(0, 0, 1, 128, e1, b1, w2, b2, out,         E);
    // nptp:  left = O_a (g_O + 0),   right = P_b (g_P + 128)
    edge_kernel<<<blocks, 256>>>(1, 0, 0, 128, e2, b1, w2, b2, out + E,     E);
    // nptnp: left = O_a (g_O + 0),   right = O_b (g_O + 128)
    edge_kernel<<<blocks, 256>>>(1, 0, 1, 128, e3, b1, w2, b2, out + 2 * E, E);
}

// round 5
// speedup vs baseline: 1.5516x; 1.5516x over previous
#include <cuda_runtime.h>
#include <cuda_bf16.h>
#include <cstdint>

#define NMAX 100000
#define HH   128
#define KTOT 384          // K of split GEMM: [hi | lo | hi]
#define KS   392          // padded smem/global row stride (bf16 elems), +16B

// Per-node projections. [node][256]: cols 0..127 = z@W1a (left), 128..255 = z@W1b (right)
__device__ float g_P[(size_t)NMAX * 256];
__device__ float g_O[(size_t)NMAX * 256];

// Pre-built B' image: [colblock(2)][n(128)][KS] bf16, rows = output column n,
// cols = K-extended [Bhi(128) | Bhi(128) | Blo(128)] (k contiguous, "col-major B").
__device__ __align__(16) __nv_bfloat16 g_Bimg[2 * 128 * KS];

// ---------------- helpers ----------------
__device__ __forceinline__ uint32_t smem_u32(const void* p) {
    uint32_t a;
    asm("{ .reg .u64 t; cvta.to.shared.u64 t, %1; cvt.u32.u64 %0, t; }"
        : "=r"(a) : "l"(p));
    return a;
}

__device__ __forceinline__ void ldsm_x4(uint32_t* r, uint32_t addr) {
    asm volatile("ldmatrix.sync.aligned.m8n8.x4.shared.b16 {%0,%1,%2,%3}, [%4];\n"
                 : "=r"(r[0]), "=r"(r[1]), "=r"(r[2]), "=r"(r[3]) : "r"(addr));
}

__device__ __forceinline__ void mma_bf16(float* c, const uint32_t* a,
                                         uint32_t b0, uint32_t b1) {
    asm volatile(
        "mma.sync.aligned.m16n8k16.row.col.f32.bf16.bf16.f32 "
        "{%0,%1,%2,%3}, {%4,%5,%6,%7}, {%8,%9}, {%0,%1,%2,%3};\n"
        : "+f"(c[0]), "+f"(c[1]), "+f"(c[2]), "+f"(c[3])
        : "r"(a[0]), "r"(a[1]), "r"(a[2]), "r"(a[3]), "r"(b0), "r"(b1));
}

__device__ __forceinline__ uint32_t pack_hi(float a, float b) {
    __nv_bfloat162 v = __floats2bfloat162_rn(a, b);
    return *reinterpret_cast<uint32_t*>(&v);
}
__device__ __forceinline__ uint32_t pack_lo(float a, float b) {
    float ah = __bfloat162float(__float2bfloat16(a));
    float bh = __bfloat162float(__float2bfloat16(b));
    __nv_bfloat162 v = __floats2bfloat162_rn(a - ah, b - bh);
    return *reinterpret_cast<uint32_t*>(&v);
}

// ---------------- prep: build B' image once ----------------
__global__ void prep_B(const float* __restrict__ w1) {
    int i = blockIdx.x * blockDim.x + threadIdx.x;   // over 2*128*384
    if (i >= 2 * 128 * KTOT) return;
    int cb = i / (128 * KTOT);
    int rem = i % (128 * KTOT);
    int nloc = rem / KTOT;
    int k = rem % KTOT;
    int kk = k & 127;
    float w = w1[(cb * 128 + kk) * 128 + nloc];
    __nv_bfloat16 v;
    if (k < 256) v = __float2bfloat16(w);                                  // hi
    else         v = __float2bfloat16(w - __bfloat162float(__float2bfloat16(w))); // lo
    g_Bimg[(size_t)cb * 128 * KS + (size_t)nloc * KS + k] = v;
}

// ---------------- GEMM: C[128 rows][128 cols] per CTA via mma.sync ----------------
// grid = (ceil(n/128), 2 colblocks, 2 matrices), 256 threads.
__global__ __launch_bounds__(256, 1)
void gemm_mma(const float* __restrict__ Zp, const float* __restrict__ Zo, int n) {
    extern __shared__ __nv_bfloat16 smem[];
    __nv_bfloat16* As = smem;                    // [128][KS]
    __nv_bfloat16* Bs = smem + 128 * KS;         // [128][KS]

    const int tid = threadIdx.x;
    const int lane = tid & 31;
    const int wid = tid >> 5;
    const int wm = wid & 3;          // 4 warps over M (32 rows each)
    const int wn = wid >> 2;         // 2 warps over N (64 cols each)

    const float* A = blockIdx.z ? Zo : Zp;
    float* C = blockIdx.z ? g_O : g_P;
    const int cb = blockIdx.y;                       // col block (0/1)
    const long rowBase = (long)blockIdx.x * 128;

    // ---- copy B' col-block (98 KB, L2-resident) ----
    {
        const uint4* src = reinterpret_cast<const uint4*>(g_Bimg + (size_t)cb * 128 * KS);
        uint4* dst = reinterpret_cast<uint4*>(Bs);
        #pragma unroll
        for (int i = 0; i < 24; i++)
            dst[tid + i * 256] = src[tid + i * 256];
        int i24 = tid + 24 * 256;
        if (i24 < 128 * KS / 8) dst[i24] = src[i24];
    }

    // ---- load A tile (128 rows x 128 fp32), split to [hi | lo | hi] bf16 ----
    {
        int row = tid >> 1;
        int half = tid & 1;                          // cols [half*64, half*64+64)
        long grow = rowBase + row;
        const float* ap = A + grow * HH + half * 64;
        __nv_bfloat16* as = As + row * KS + half * 64;
        #pragma unroll
        for (int j = 0; j < 8; j++) {                // 8 floats per step
            float4 v0, v1;
            if (grow < n) {
                v0 = reinterpret_cast<const float4*>(ap)[2 * j];
                v1 = reinterpret_cast<const float4*>(ap)[2 * j + 1];
            } else {
                v0 = make_float4(0.f, 0.f, 0.f, 0.f); v1 = v0;
            }
            uint4 h, l;
            h.x = pack_hi(v0.x, v0.y); h.y = pack_hi(v0.z, v0.w);
            h.z = pack_hi(v1.x, v1.y); h.w = pack_hi(v1.z, v1.w);
            l.x = pack_lo(v0.x, v0.y); l.y = pack_lo(v0.z, v0.w);
            l.z = pack_lo(v1.x, v1.y); l.w = pack_lo(v1.z, v1.w);
            *reinterpret_cast<uint4*>(as + j * 8)       = h;   // hi  (k 0..127)
            *reinterpret_cast<uint4*>(as + 128 + j * 8) = l;   // lo  (k 128..255)
            *reinterpret_cast<uint4*>(as + 256 + j * 8) = h;   // hi  (k 256..383)
        }
    }
    __syncthreads();

    // ---- compute: 24 k-steps of m16n8k16, warp tile 32x64 ----
    const uint32_t sbA = smem_u32(As);
    const uint32_t sbB = smem_u32(Bs);
    uint32_t a_base[2], b_base[4];
    #pragma unroll
    for (int tm = 0; tm < 2; tm++)
        a_base[tm] = sbA + ((wm * 32 + tm * 16 + (lane & 15)) * KS
                            + (lane >> 4) * 8) * 2;
    #pragma unroll
    for (int np = 0; np < 4; np++)
        b_base[np] = sbB + ((wn * 64 + np * 16 + ((lane >> 4) << 3) + (lane & 7)) * KS
                            + ((lane >> 3) & 1) * 8) * 2;

    float acc[2][8][4];
    #pragma unroll
    for (int tm = 0; tm < 2; tm++)
        #pragma unroll
        for (int tn = 0; tn < 8; tn++)
            #pragma unroll
            for (int q = 0; q < 4; q++) acc[tm][tn][q] = 0.f;

    #pragma unroll 2
    for (int ks = 0; ks < 24; ks++) {
        uint32_t a[2][4], b[4][4];
        #pragma unroll
        for (int tm = 0; tm < 2; tm++) ldsm_x4(a[tm], a_base[tm] + ks * 32);
        #pragma unroll
        for (int np = 0; np < 4; np++) ldsm_x4(b[np], b_base[np] + ks * 32);
        #pragma unroll
        for (int tm = 0; tm < 2; tm++)
            #pragma unroll
            for (int tn = 0; tn < 8; tn++)
                mma_bf16(acc[tm][tn], a[tm],
                         b[tn >> 1][(tn & 1) * 2], b[tn >> 1][(tn & 1) * 2 + 1]);
    }

    // ---- epilogue: write fp32 C ----
    #pragma unroll
    for (int tm = 0; tm < 2; tm++) {
        long r0 = rowBase + wm * 32 + tm * 16 + (lane >> 2);
        long r1 = r0 + 8;
        int col = cb * 128 + wn * 64 + (lane & 3) * 2;
        #pragma unroll
        for (int tn = 0; tn < 8; tn++) {
            if (r0 < n)
                *reinterpret_cast<float2*>(C + r0 * 256 + col + tn * 8) =
                    make_float2(acc[tm][tn][0], acc[tm][tn][1]);
            if (r1 < n)
                *reinterpret_cast<float2*>(C + r1 * 256 + col + tn * 8) =
                    make_float2(acc[tm][tn][2], acc[tm][tn][3]);
        }
    }
}

// ---------------- edge decode: all 3 types, 16 lanes per edge ----------------
__global__ __launch_bounds__(256)
void edge_all(const int* __restrict__ e1, const int* __restrict__ e2,
              const int* __restrict__ e3,
              const float* __restrict__ b1, const float* __restrict__ w2,
              const float* __restrict__ b2, float* __restrict__ out, int E) {
    const int tid = threadIdx.x;
    const int lane = tid & 31;
    const int l = lane & 15;
    const int half = lane >> 4;
    long e = ((long)blockIdx.x * 8 + (tid >> 5)) * 2 + half;   // edge id in [0,3E)
    if (e >= 3L * E) return;

    int type = (e >= 2L * E) ? 2 : (e >= (long)E ? 1 : 0);
    int eloc = (int)(e - (long)type * E);
    const int* idx = (type == 0) ? e1 : ((type == 1) ? e2 : e3);
    const float* X = (type == 0) ? g_P : g_O;          // left proj (cols 0..127)
    const float* Y = ((type == 1) ? g_P : g_O) + 128;  // right proj (cols 128..255)

    int s = idx[eloc];
    int d = idx[eloc + E];
    const float* xr = X + (size_t)s * 256;
    const float* yr = Y + (size_t)d * 256;

    float4 x1 = *reinterpret_cast<const float4*>(xr + l * 4);
    float4 x2 = *reinterpret_cast<const float4*>(xr + 64 + l * 4);
    float4 y1 = *reinterpret_cast<const float4*>(yr + l * 4);
    float4 y2 = *reinterpret_cast<const float4*>(yr + 64 + l * 4);
    float4 ba = *reinterpret_cast<const float4*>(b1 + l * 4);
    float4 bb = *reinterpret_cast<const float4*>(b1 + 64 + l * 4);
    float4 wa = *reinterpret_cast<const float4*>(w2 + l * 4);
    float4 wb = *reinterpret_cast<const float4*>(w2 + 64 + l * 4);

    float t, sum;
    t = x1.x + y1.x + ba.x; sum  = fmaxf(t, 0.f) * wa.x;
    t = x1.y + y1.y + ba.y; sum += fmaxf(t, 0.f) * wa.y;
    t = x1.z + y1.z + ba.z; sum += fmaxf(t, 0.f) * wa.z;
    t = x1.w + y1.w + ba.w; sum += fmaxf(t, 0.f) * wa.w;
    t = x2.x + y2.x + bb.x; sum += fmaxf(t, 0.f) * wb.x;
    t = x2.y + y2.y + bb.y; sum += fmaxf(t, 0.f) * wb.y;
    t = x2.z + y2.z + bb.z; sum += fmaxf(t, 0.f) * wb.z;
    t = x2.w + y2.w + bb.w; sum += fmaxf(t, 0.f) * wb.w;

    sum += __shfl_xor_sync(0xffffffffu, sum, 8);
    sum += __shfl_xor_sync(0xffffffffu, sum, 4);
    sum += __shfl_xor_sync(0xffffffffu, sum, 2);
    sum += __shfl_xor_sync(0xffffffffu, sum, 1);

    if (l == 0)
        out[e] = sum + __ldg(b2);
}

extern "C" void kernel_launch(void* const* d_in, const int* in_sizes, int n_in,
                              void* d_out, int out_size) {
    const float* z_p = (const float*)d_in[0];
    const float* z_o = (const float*)d_in[1];
    const int*   e1  = (const int*)d_in[2];   // ptnp:  pnode src, onode dst
    const int*   e2  = (const int*)d_in[3];   // nptp:  onode src, pnode dst
    const int*   e3  = (const int*)d_in[4];   // nptnp: onode src, onode dst
    const float* w1  = (const float*)d_in[5];
    const float* b1  = (const float*)d_in[6];
    const float* w2  = (const float*)d_in[7];
    const float* b2  = (const float*)d_in[8];
    float* out = (float*)d_out;

    const int n = in_sizes[0] / HH;       // 100000
    const int E = in_sizes[2] / 2;        // 500000
    (void)n_in; (void)out_size;

    const int smemBytes = 2 * 128 * KS * 2;   // 200704 B
    static int configured = 0;
    cudaFuncSetAttribute(gemm_mma, cudaFuncAttributeMaxDynamicSharedMemorySize,
                         smemBytes);
    (void)configured;

    prep_B<<<(2 * 128 * KTOT + 255) / 256, 256>>>(w1);

    dim3 g((n + 127) / 128, 2, 2);
    gemm_mma<<<g, 256, smemBytes>>>(z_p, z_o, n);

    long totalE = 3L * E;
    int blocks = (int)((totalE + 15) / 16);   // 2 edges per warp, 8 warps per block
    edge_all<<<blocks, 256>>>(e1, e2, e3, b1, w2, b2, out, E);
}

// round 6
// speedup vs baseline: 1.6451x; 1.0602x over previous
#include <cuda_runtime.h>
#include <cuda_bf16.h>
#include <cuda_fp16.h>
#include <cstdint>

#define NMAX 100000
#define HH   128
#define KTOT 384          // K of split GEMM: [hi | lo | hi]
#define KS   392          // padded row stride (bf16 elems), +16B vs 384

// Per-node projections (fp16). [node][256]: cols 0..127 = z@W1a (left/src),
// cols 128..255 = z@W1b (right/dst).
__device__ __half g_P[(size_t)NMAX * 256];
__device__ __half g_O[(size_t)NMAX * 256];

// Pre-built B' image: [n(256 output cols)][KS] bf16, K-extended [Bhi|Bhi|Blo].
__device__ __align__(16) __nv_bfloat16 g_Bimg[256 * KS];

// ---------------- helpers ----------------
__device__ __forceinline__ uint32_t smem_u32(const void* p) {
    uint32_t a;
    asm("{ .reg .u64 t; cvta.to.shared.u64 t, %1; cvt.u32.u64 %0, t; }"
        : "=r"(a) : "l"(p));
    return a;
}

__device__ __forceinline__ void ldsm_x4(uint32_t* r, uint32_t addr) {
    asm volatile("ldmatrix.sync.aligned.m8n8.x4.shared.b16 {%0,%1,%2,%3}, [%4];\n"
                 : "=r"(r[0]), "=r"(r[1]), "=r"(r[2]), "=r"(r[3]) : "r"(addr));
}

__device__ __forceinline__ void mma_bf16(float* c, const uint32_t* a,
                                         uint32_t b0, uint32_t b1) {
    asm volatile(
        "mma.sync.aligned.m16n8k16.row.col.f32.bf16.bf16.f32 "
        "{%0,%1,%2,%3}, {%4,%5,%6,%7}, {%8,%9}, {%0,%1,%2,%3};\n"
        : "+f"(c[0]), "+f"(c[1]), "+f"(c[2]), "+f"(c[3])
        : "r"(a[0]), "r"(a[1]), "r"(a[2]), "r"(a[3]), "r"(b0), "r"(b1));
}

__device__ __forceinline__ uint32_t pack_hi(float a, float b) {
    __nv_bfloat162 v = __floats2bfloat162_rn(a, b);
    return *reinterpret_cast<uint32_t*>(&v);
}
__device__ __forceinline__ uint32_t pack_lo(float a, float b) {
    float ah = __bfloat162float(__float2bfloat16(a));
    float bh = __bfloat162float(__float2bfloat16(b));
    __nv_bfloat162 v = __floats2bfloat162_rn(a - ah, b - bh);
    return *reinterpret_cast<uint32_t*>(&v);
}

// ---------------- prep: build B' image once ----------------
__global__ void prep_B(const float* __restrict__ w1) {
    int i = blockIdx.x * blockDim.x + threadIdx.x;   // over 256*384
    if (i >= 256 * KTOT) return;
    int nn = i / KTOT;            // output col 0..255
    int k = i % KTOT;
    int kk = k & 127;
    int cb = nn >> 7;             // which half of w1 columns-stack
    int nloc = nn & 127;
    float w = w1[(cb * 128 + kk) * 128 + nloc];
    __nv_bfloat16 v;
    if (k < 256) v = __float2bfloat16(w);                                           // hi
    else         v = __float2bfloat16(w - __bfloat162float(__float2bfloat16(w)));   // lo
    g_Bimg[(size_t)nn * KS + k] = v;
}

// ---------------- GEMM: C[128 rows][256 cols] per CTA via mma.sync ----------------
// grid = (ceil(n/128), 2 matrices), 256 threads. B streamed in 4 chunks of 64 cols.
__global__ __launch_bounds__(256, 1)
void gemm_mma(const float* __restrict__ Zp, const float* __restrict__ Zo, int n) {
    extern __shared__ __nv_bfloat16 smem[];
    __nv_bfloat16* As = smem;                       // [128][KS]
    __nv_bfloat16* Bs[2] = { smem + 128 * KS,       // [64][KS] buf0
                             smem + 192 * KS };     // [64][KS] buf1

    const int tid = threadIdx.x;
    const int lane = tid & 31;
    const int wid = tid >> 5;
    const int wm = wid & 3;          // 4 warps over M (32 rows)
    const int wn = wid >> 2;         // 2 warps over 32-col halves of a 64-col chunk

    const float* A = blockIdx.y ? Zo : Zp;
    __half* C = blockIdx.y ? g_O : g_P;
    const long rowBase = (long)blockIdx.x * 128;

    // -- async-copy one 64-col chunk of B' into a buffer --
    auto cpchunk = [&](int c, __nv_bfloat16* dst) {
        const __nv_bfloat16* src = g_Bimg + (size_t)c * 64 * KS;
        uint32_t d = smem_u32(dst);
        for (int i = tid; i < 64 * KS / 8; i += 256)
            asm volatile("cp.async.cg.shared.global [%0], [%1], 16;\n"
                         :: "r"(d + i * 16), "l"(src + i * 8) : "memory");
    };

    cpchunk(0, Bs[0]);
    asm volatile("cp.async.commit_group;\n" ::: "memory");
    cpchunk(1, Bs[1]);
    asm volatile("cp.async.commit_group;\n" ::: "memory");

    // ---- load A tile (128 rows x 128 fp32), split to [hi | lo | hi] bf16 ----
    {
        int row = tid >> 1;
        int half = tid & 1;                          // cols [half*64, half*64+64)
        long grow = rowBase + row;
        const float* ap = A + grow * HH + half * 64;
        __nv_bfloat16* as = As + row * KS + half * 64;
        #pragma unroll
        for (int j = 0; j < 8; j++) {
            float4 v0, v1;
            if (grow < n) {
                v0 = reinterpret_cast<const float4*>(ap)[2 * j];
                v1 = reinterpret_cast<const float4*>(ap)[2 * j + 1];
            } else {
                v0 = make_float4(0.f, 0.f, 0.f, 0.f); v1 = v0;
            }
            uint4 h, l;
            h.x = pack_hi(v0.x, v0.y); h.y = pack_hi(v0.z, v0.w);
            h.z = pack_hi(v1.x, v1.y); h.w = pack_hi(v1.z, v1.w);
            l.x = pack_lo(v0.x, v0.y); l.y = pack_lo(v0.z, v0.w);
            l.z = pack_lo(v1.x, v1.y); l.w = pack_lo(v1.z, v1.w);
            *reinterpret_cast<uint4*>(as + j * 8)       = h;   // hi  (k 0..127)
            *reinterpret_cast<uint4*>(as + 128 + j * 8) = l;   // lo  (k 128..255)
            *reinterpret_cast<uint4*>(as + 256 + j * 8) = h;   // hi  (k 256..383)
        }
    }

    // wait chunk0 (chunk1 may still be in flight)
    asm volatile("cp.async.wait_group 1;\n" ::: "memory");
    __syncthreads();

    const uint32_t sbA = smem_u32(As);
    const uint32_t sbB[2] = { smem_u32(Bs[0]), smem_u32(Bs[1]) };
    uint32_t a_base[2], b_off[2];
    #pragma unroll
    for (int tm = 0; tm < 2; tm++)
        a_base[tm] = sbA + ((wm * 32 + tm * 16 + (lane & 15)) * KS
                            + (lane >> 4) * 8) * 2;
    #pragma unroll
    for (int np = 0; np < 2; np++)
        b_off[np] = ((wn * 32 + np * 16 + ((lane >> 4) << 3) + (lane & 7)) * KS
                      + ((lane >> 3) & 1) * 8) * 2;

    for (int c = 0; c < 4; c++) {
        const uint32_t bb = sbB[c & 1];
        float acc[2][4][4];
        #pragma unroll
        for (int tm = 0; tm < 2; tm++)
            #pragma unroll
            for (int tn = 0; tn < 4; tn++)
                #pragma unroll
                for (int q = 0; q < 4; q++) acc[tm][tn][q] = 0.f;

        #pragma unroll 2
        for (int ks = 0; ks < 24; ks++) {
            uint32_t a[2][4], b[2][4];
            #pragma unroll
            for (int tm = 0; tm < 2; tm++) ldsm_x4(a[tm], a_base[tm] + ks * 32);
            #pragma unroll
            for (int np = 0; np < 2; np++) ldsm_x4(b[np], bb + b_off[np] + ks * 32);
            #pragma unroll
            for (int tm = 0; tm < 2; tm++)
                #pragma unroll
                for (int tn = 0; tn < 4; tn++)
                    mma_bf16(acc[tm][tn], a[tm],
                             b[tn >> 1][(tn & 1) * 2], b[tn >> 1][(tn & 1) * 2 + 1]);
        }

        __syncthreads();   // everyone done reading this buffer
        if (c + 2 < 4) {
            cpchunk(c + 2, Bs[c & 1]);
            asm volatile("cp.async.commit_group;\n" ::: "memory");
        }

        // ---- epilogue for this 64-col chunk: fp32 acc -> fp16 C ----
        #pragma unroll
        for (int tm = 0; tm < 2; tm++) {
            long r0 = rowBase + wm * 32 + tm * 16 + (lane >> 2);
            long r1 = r0 + 8;
            int col = c * 64 + wn * 32 + (lane & 3) * 2;
            #pragma unroll
            for (int tn = 0; tn < 4; tn++) {
                if (r0 < n) {
                    __half2 v = __floats2half2_rn(acc[tm][tn][0], acc[tm][tn][1]);
                    *reinterpret_cast<__half2*>(C + r0 * 256 + col + tn * 8) = v;
                }
                if (r1 < n) {
                    __half2 v = __floats2half2_rn(acc[tm][tn][2], acc[tm][tn][3]);
                    *reinterpret_cast<__half2*>(C + r1 * 256 + col + tn * 8) = v;
                }
            }
        }

        // make next chunk visible before using it
        if (c == 2) {
            asm volatile("cp.async.wait_group 0;\n" ::: "memory");
        } else if (c < 2) {
            asm volatile("cp.async.wait_group 1;\n" ::: "memory");
        }
        __syncthreads();
    }
}

// ---------------- edge decode: all 3 types, 8 lanes per edge ----------------
__global__ __launch_bounds__(256)
void edge_all(const int* __restrict__ e1, const int* __restrict__ e2,
              const int* __restrict__ e3,
              const float* __restrict__ b1, const float* __restrict__ w2,
              const float* __restrict__ b2, float* __restrict__ out, int E) {
    const int tid = threadIdx.x;
    const int lane = tid & 31;
    const int l = lane & 7;          // lane within 8-lane edge group
    const int sub = lane >> 3;       // which of 4 edges in this warp
    long w = (long)blockIdx.x * 8 + (tid >> 5);
    long e = w * 4 + sub;
    if (e >= 3L * E) return;

    int type = (e >= 2L * E) ? 2 : (e >= (long)E ? 1 : 0);
    int eloc = (int)(e - (long)type * E);
    const int* idx = (type == 0) ? e1 : ((type == 1) ? e2 : e3);
    const __half* X = (type == 0) ? g_P : g_O;          // left proj (cols 0..127)
    const __half* Y = ((type == 1) ? g_P : g_O) + 128;  // right proj (cols 128..255)

    int s = idx[eloc];
    int d = idx[eloc + E];
    const __half* xr = X + (size_t)s * 256 + l * 16;
    const __half* yr = Y + (size_t)d * 256 + l * 16;

    // 4 independent 16B gathers per lane
    uint4 xa = *reinterpret_cast<const uint4*>(xr);
    uint4 xb = *reinterpret_cast<const uint4*>(xr + 8);
    uint4 ya = *reinterpret_cast<const uint4*>(yr);
    uint4 yb = *reinterpret_cast<const uint4*>(yr + 8);

    float bx[16], wx[16];
    #pragma unroll
    for (int j = 0; j < 4; j++) {
        float4 bv = reinterpret_cast<const float4*>(b1 + l * 16)[j];
        float4 wv = reinterpret_cast<const float4*>(w2 + l * 16)[j];
        bx[4 * j + 0] = bv.x; bx[4 * j + 1] = bv.y; bx[4 * j + 2] = bv.z; bx[4 * j + 3] = bv.w;
        wx[4 * j + 0] = wv.x; wx[4 * j + 1] = wv.y; wx[4 * j + 2] = wv.z; wx[4 * j + 3] = wv.w;
    }

    const __half2* xh = reinterpret_cast<const __half2*>(&xa);
    const __half2* yh = reinterpret_cast<const __half2*>(&ya);
    float sum = 0.f;
    #pragma unroll
    for (int p = 0; p < 8; p++) {
        float2 xf = __half22float2(p < 4 ? xh[p] : reinterpret_cast<const __half2*>(&xb)[p - 4]);
        float2 yf = __half22float2(p < 4 ? yh[p] : reinterpret_cast<const __half2*>(&yb)[p - 4]);
        float t0 = xf.x + yf.x + bx[2 * p];
        float t1 = xf.y + yf.y + bx[2 * p + 1];
        sum = fmaf(fmaxf(t0, 0.f), wx[2 * p], sum);
        sum = fmaf(fmaxf(t1, 0.f), wx[2 * p + 1], sum);
    }

    sum += __shfl_xor_sync(0xffffffffu, sum, 4);
    sum += __shfl_xor_sync(0xffffffffu, sum, 2);
    sum += __shfl_xor_sync(0xffffffffu, sum, 1);

    if (l == 0)
        out[e] = sum + __ldg(b2);
}

extern "C" void kernel_launch(void* const* d_in, const int* in_sizes, int n_in,
                              void* d_out, int out_size) {
    const float* z_p = (const float*)d_in[0];
    const float* z_o = (const float*)d_in[1];
    const int*   e1  = (const int*)d_in[2];   // ptnp:  pnode src, onode dst
    const int*   e2  = (const int*)d_in[3];   // nptp:  onode src, pnode dst
    const int*   e3  = (const int*)d_in[4];   // nptnp: onode src, onode dst
    const float* w1  = (const float*)d_in[5];
    const float* b1  = (const float*)d_in[6];
    const float* w2  = (const float*)d_in[7];
    const float* b2  = (const float*)d_in[8];
    float* out = (float*)d_out;

    const int n = in_sizes[0] / HH;       // 100000
    const int E = in_sizes[2] / 2;        // 500000
    (void)n_in; (void)out_size;

    const int smemBytes = 256 * KS * 2;   // As(128) + 2x Bs(64) rows = 200704 B
    cudaFuncSetAttribute(gemm_mma, cudaFuncAttributeMaxDynamicSharedMemorySize,
                         smemBytes);

    prep_B<<<(256 * KTOT + 255) / 256, 256>>>(w1);

    dim3 g((n + 127) / 128, 2);
    gemm_mma<<<g, 256, smemBytes>>>(z_p, z_o, n);

    long totalE = 3L * E;
    int blocks = (int)((totalE + 31) / 32);   // 4 edges/warp, 8 warps/block
    edge_all<<<blocks, 256>>>(e1, e2, e3, b1, w2, b2, out, E);
}

// round 8
// speedup vs baseline: 2.8827x; 1.7523x over previous
#include <cuda_runtime.h>
#include <cuda_fp16.h>
#include <cstdint>

#define NMAX 100000
#define HH   128
#define KS2  264          // padded row stride (half elems) for K=256 tiles

// Per-node projections (fp16). [node][256]: cols 0..127 = z@W1a (left/src),
// cols 128..255 = z@W1b + b1 (right/dst, bias folded).
__device__ __half g_P[(size_t)NMAX * 256];
__device__ __half g_O[(size_t)NMAX * 256];

// Pre-built B' image: [n(256 output cols)][KS2] fp16, K-extended [Bh | Bh].
__device__ __align__(16) __half g_Bimg[256 * KS2];

// ---------------- helpers ----------------
__device__ __forceinline__ uint32_t smem_u32(const void* p) {
    uint32_t a;
    asm("{ .reg .u64 t; cvta.to.shared.u64 t, %1; cvt.u32.u64 %0, t; }"
        : "=r"(a) : "l"(p));
    return a;
}

__device__ __forceinline__ void ldsm_x4(uint32_t* r, uint32_t addr) {
    asm volatile("ldmatrix.sync.aligned.m8n8.x4.shared.b16 {%0,%1,%2,%3}, [%4];\n"
                 : "=r"(r[0]), "=r"(r[1]), "=r"(r[2]), "=r"(r[3]) : "r"(addr));
}

__device__ __forceinline__ void mma_f16(float* c, const uint32_t* a,
                                        uint32_t b0, uint32_t b1) {
    asm volatile(
        "mma.sync.aligned.m16n8k16.row.col.f32.f16.f16.f32 "
        "{%0,%1,%2,%3}, {%4,%5,%6,%7}, {%8,%9}, {%0,%1,%2,%3};\n"
        : "+f"(c[0]), "+f"(c[1]), "+f"(c[2]), "+f"(c[3])
        : "r"(a[0]), "r"(a[1]), "r"(a[2]), "r"(a[3]), "r"(b0), "r"(b1));
}

// 32B gather load, pinned in L2 (evict_last requires v8.b32 on this ptxas)
__device__ __forceinline__ void ldg_el8(const void* p, uint4& a, uint4& b) {
    asm volatile(
        "ld.global.nc.L2::evict_last.v8.b32 {%0,%1,%2,%3,%4,%5,%6,%7}, [%8];"
        : "=r"(a.x), "=r"(a.y), "=r"(a.z), "=r"(a.w),
          "=r"(b.x), "=r"(b.y), "=r"(b.z), "=r"(b.w)
        : "l"(p));
}

// ---------------- prep: build B' image once ----------------
__global__ void prep_B(const float* __restrict__ w1) {
    int i = blockIdx.x * blockDim.x + threadIdx.x;   // over 256*128
    if (i >= 256 * 128) return;
    int nn = i >> 7;            // output col 0..255
    int k = i & 127;
    int cb = nn >> 7;
    int nloc = nn & 127;
    __half h = __float2half_rn(w1[(cb * 128 + k) * 128 + nloc]);
    g_Bimg[(size_t)nn * KS2 + k] = h;          // term 1: Ah * Bh
    g_Bimg[(size_t)nn * KS2 + 128 + k] = h;    // term 2: Al * Bh
}

// ---------------- GEMM: C[128 rows][256 cols] per CTA via mma.sync ----------------
// grid = (ceil(n/128), 2 matrices), 256 threads. B streamed in 4 chunks of 64 cols.
__global__ __launch_bounds__(256, 1)
void gemm_mma(const float* __restrict__ Zp, const float* __restrict__ Zo,
              const float* __restrict__ b1, int n) {
    extern __shared__ __half smem[];
    __half* As = smem;                       // [128][KS2]  ([Ah | Al])
    __half* Bs[2] = { smem + 128 * KS2,      // [64][KS2] buf0
                      smem + 192 * KS2 };    // [64][KS2] buf1

    const int tid = threadIdx.x;
    const int lane = tid & 31;
    const int wid = tid >> 5;
    const int wm = wid & 3;          // 4 warps over M (32 rows)
    const int wn = wid >> 2;         // 2 warps over 32-col halves of chunk

    const float* A = blockIdx.y ? Zo : Zp;
    __half* C = blockIdx.y ? g_O : g_P;
    const long rowBase = (long)blockIdx.x * 128;

    auto cpchunk = [&](int c, __half* dst) {
        const __half* src = g_Bimg + (size_t)c * 64 * KS2;
        uint32_t d = smem_u32(dst);
        for (int i = tid; i < 64 * KS2 / 8; i += 256)
            asm volatile("cp.async.cg.shared.global [%0], [%1], 16;\n"
                         :: "r"(d + i * 16), "l"(src + i * 8) : "memory");
    };

    cpchunk(0, Bs[0]);
    asm volatile("cp.async.commit_group;\n" ::: "memory");
    cpchunk(1, Bs[1]);
    asm volatile("cp.async.commit_group;\n" ::: "memory");

    // ---- load A tile (128 rows x 128 fp32), split to [Ah | Al] fp16 ----
    {
        int row = tid >> 1;
        int half = tid & 1;                          // cols [half*64, half*64+64)
        long grow = rowBase + row;
        const float* ap = A + grow * HH + half * 64;
        __half* as = As + row * KS2 + half * 64;
        #pragma unroll
        for (int j = 0; j < 16; j++) {
            float4 v = (grow < n) ? reinterpret_cast<const float4*>(ap)[j]
                                  : make_float4(0.f, 0.f, 0.f, 0.f);
            __half2 h0 = __floats2half2_rn(v.x, v.y);
            __half2 h1 = __floats2half2_rn(v.z, v.w);
            float2 f0 = __half22float2(h0);
            float2 f1 = __half22float2(h1);
            __half2 l0 = __floats2half2_rn(v.x - f0.x, v.y - f0.y);
            __half2 l1 = __floats2half2_rn(v.z - f1.x, v.w - f1.y);
            uint2 hh, ll;
            hh.x = *reinterpret_cast<uint32_t*>(&h0);
            hh.y = *reinterpret_cast<uint32_t*>(&h1);
            ll.x = *reinterpret_cast<uint32_t*>(&l0);
            ll.y = *reinterpret_cast<uint32_t*>(&l1);
            *reinterpret_cast<uint2*>(as + j * 4)       = hh;   // Ah (k 0..127)
            *reinterpret_cast<uint2*>(as + 128 + j * 4) = ll;   // Al (k 128..255)
        }
    }

    asm volatile("cp.async.wait_group 1;\n" ::: "memory");
    __syncthreads();

    const uint32_t sbA = smem_u32(As);
    const uint32_t sbB[2] = { smem_u32(Bs[0]), smem_u32(Bs[1]) };
    uint32_t a_base[2], b_off[2];
    #pragma unroll
    for (int tm = 0; tm < 2; tm++)
        a_base[tm] = sbA + ((wm * 32 + tm * 16 + (lane & 15)) * KS2
                            + (lane >> 4) * 8) * 2;
    #pragma unroll
    for (int np = 0; np < 2; np++)
        b_off[np] = ((wn * 32 + np * 16 + ((lane >> 4) << 3) + (lane & 7)) * KS2
                      + ((lane >> 3) & 1) * 8) * 2;

    for (int c = 0; c < 4; c++) {
        const uint32_t bb = sbB[c & 1];
        float acc[2][4][4];
        #pragma unroll
        for (int tm = 0; tm < 2; tm++)
            #pragma unroll
            for (int tn = 0; tn < 4; tn++)
                #pragma unroll
                for (int q = 0; q < 4; q++) acc[tm][tn][q] = 0.f;

        #pragma unroll 2
        for (int ks = 0; ks < 16; ks++) {
            uint32_t a[2][4], b[2][4];
            #pragma unroll
            for (int tm = 0; tm < 2; tm++) ldsm_x4(a[tm], a_base[tm] + ks * 32);
            #pragma unroll
            for (int np = 0; np < 2; np++) ldsm_x4(b[np], bb + b_off[np] + ks * 32);
            #pragma unroll
            for (int tm = 0; tm < 2; tm++)
                #pragma unroll
                for (int tn = 0; tn < 4; tn++)
                    mma_f16(acc[tm][tn], a[tm],
                            b[tn >> 1][(tn & 1) * 2], b[tn >> 1][(tn & 1) * 2 + 1]);
        }

        __syncthreads();   // everyone done reading this buffer
        if (c + 2 < 4) {
            cpchunk(c + 2, Bs[c & 1]);
            asm volatile("cp.async.commit_group;\n" ::: "memory");
        }

        // ---- epilogue: fp32 acc (+b1 on right half) -> fp16 C ----
        #pragma unroll
        for (int tm = 0; tm < 2; tm++) {
            long r0 = rowBase + wm * 32 + tm * 16 + (lane >> 2);
            long r1 = r0 + 8;
            int colBase = c * 64 + wn * 32 + (lane & 3) * 2;
            #pragma unroll
            for (int tn = 0; tn < 4; tn++) {
                int col = colBase + tn * 8;
                float bx = 0.f, by = 0.f;
                if (col >= 128) {                       // right half: fold b1
                    float2 bv = *reinterpret_cast<const float2*>(b1 + col - 128);
                    bx = bv.x; by = bv.y;
                }
                if (r0 < n) {
                    __half2 v = __floats2half2_rn(acc[tm][tn][0] + bx,
                                                  acc[tm][tn][1] + by);
                    *reinterpret_cast<__half2*>(C + r0 * 256 + col) = v;
                }
                if (r1 < n) {
                    __half2 v = __floats2half2_rn(acc[tm][tn][2] + bx,
                                                  acc[tm][tn][3] + by);
                    *reinterpret_cast<__half2*>(C + r1 * 256 + col) = v;
                }
            }
        }

        if (c == 2) {
            asm volatile("cp.async.wait_group 0;\n" ::: "memory");
        } else if (c < 2) {
            asm volatile("cp.async.wait_group 1;\n" ::: "memory");
        }
        __syncthreads();
    }
}

// ---------------- edge decode: 8 lanes per edge, 2 edges per lane-group ----------------
__global__ __launch_bounds__(256)
void edge_all(const int* __restrict__ e1, const int* __restrict__ e2,
              const int* __restrict__ e3,
              const float* __restrict__ w2, const float* __restrict__ b2,
              float* __restrict__ out, int E) {
    const int tid = threadIdx.x;
    const int l = tid & 7;
    long g = (((long)blockIdx.x << 8) + tid) >> 3;   // lane-group id
    long eA = 2 * g;
    long eB = eA + 1;
    const long TE = 3L * E;
    if (eA >= TE) return;                            // TE even -> eB valid too

    // resolve edge A
    int tA = (eA >= 2L * E) ? 2 : (eA >= (long)E ? 1 : 0);
    int lA = (int)(eA - (long)tA * E);
    const int* iA = (tA == 0) ? e1 : ((tA == 1) ? e2 : e3);
    const __half* XA = (tA == 0) ? g_P : g_O;
    const __half* YA = ((tA == 1) ? g_P : g_O) + 128;
    // resolve edge B
    int tB = (eB >= 2L * E) ? 2 : (eB >= (long)E ? 1 : 0);
    int lB = (int)(eB - (long)tB * E);
    const int* iB = (tB == 0) ? e1 : ((tB == 1) ? e2 : e3);
    const __half* XB = (tB == 0) ? g_P : g_O;
    const __half* YB = ((tB == 1) ? g_P : g_O) + 128;

    int sA = iA[lA], dA = iA[lA + E];
    int sB = iB[lB], dB = iB[lB + E];

    const __half* xrA = XA + (size_t)sA * 256 + l * 16;
    const __half* yrA = YA + (size_t)dA * 256 + l * 16;
    const __half* xrB = XB + (size_t)sB * 256 + l * 16;
    const __half* yrB = YB + (size_t)dB * 256 + l * 16;

    // 4 independent 32B gathers in flight
    uint4 xa0, xa1, ya0, ya1, xb0, xb1, yb0, yb1;
    ldg_el8(xrA, xa0, xa1);
    ldg_el8(yrA, ya0, ya1);
    ldg_el8(xrB, xb0, xb1);
    ldg_el8(yrB, yb0, yb1);

    float2 w2v[8];
    #pragma unroll
    for (int j = 0; j < 4; j++) {
        float4 wv = reinterpret_cast<const float4*>(w2 + l * 16)[j];
        w2v[2 * j]     = make_float2(wv.x, wv.y);
        w2v[2 * j + 1] = make_float2(wv.z, wv.w);
    }
    const __half2 z2 = __float2half2_rn(0.f);

    const __half2* hxA0 = reinterpret_cast<const __half2*>(&xa0);
    const __half2* hxA1 = reinterpret_cast<const __half2*>(&xa1);
    const __half2* hyA0 = reinterpret_cast<const __half2*>(&ya0);
    const __half2* hyA1 = reinterpret_cast<const __half2*>(&ya1);
    const __half2* hxB0 = reinterpret_cast<const __half2*>(&xb0);
    const __half2* hxB1 = reinterpret_cast<const __half2*>(&xb1);
    const __half2* hyB0 = reinterpret_cast<const __half2*>(&yb0);
    const __half2* hyB1 = reinterpret_cast<const __half2*>(&yb1);

    float sA0 = 0.f, sA1 = 0.f, sB0 = 0.f, sB1 = 0.f;
    #pragma unroll
    for (int p = 0; p < 8; p++) {
        __half2 xA = (p < 4) ? hxA0[p] : hxA1[p - 4];
        __half2 yA = (p < 4) ? hyA0[p] : hyA1[p - 4];
        __half2 xB = (p < 4) ? hxB0[p] : hxB1[p - 4];
        __half2 yB = (p < 4) ? hyB0[p] : hyB1[p - 4];
        float2 rA = __half22float2(__hmax2(__hadd2(xA, yA), z2));
        float2 rB = __half22float2(__hmax2(__hadd2(xB, yB), z2));
        sA0 = fmaf(rA.x, w2v[p].x, sA0);
        sA1 = fmaf(rA.y, w2v[p].y, sA1);
        sB0 = fmaf(rB.x, w2v[p].x, sB0);
        sB1 = fmaf(rB.y, w2v[p].y, sB1);
    }
    float sumA = sA0 + sA1;
    float sumB = sB0 + sB1;

    #pragma unroll
    for (int o = 4; o > 0; o >>= 1) {
        sumA += __shfl_xor_sync(0xffffffffu, sumA, o);
        sumB += __shfl_xor_sync(0xffffffffu, sumB, o);
    }

    float bias = __ldg(b2);
    if (l == 0) out[eA] = sumA + bias;
    if (l == 1) out[eB] = sumB + bias;
}

extern "C" void kernel_launch(void* const* d_in, const int* in_sizes, int n_in,
                              void* d_out, int out_size) {
    const float* z_p = (const float*)d_in[0];
    const float* z_o = (const float*)d_in[1];
    const int*   e1  = (const int*)d_in[2];   // ptnp:  pnode src, onode dst
    const int*   e2  = (const int*)d_in[3];   // nptp:  onode src, pnode dst
    const int*   e3  = (const int*)d_in[4];   // nptnp: onode src, onode dst
    const float* w1  = (const float*)d_in[5];
    const float* b1  = (const float*)d_in[6];
    const float* w2  = (const float*)d_in[7];
    const float* b2  = (const float*)d_in[8];
    float* out = (float*)d_out;

    const int n = in_sizes[0] / HH;       // 100000
    const int E = in_sizes[2] / 2;        // 500000
    (void)n_in; (void)out_size;

    const int smemBytes = (128 * KS2 + 2 * 64 * KS2) * 2;   // 135168 B
    cudaFuncSetAttribute(gemm_mma, cudaFuncAttributeMaxDynamicSharedMemorySize,
                         smemBytes);

    prep_B<<<(256 * 128 + 255) / 256, 256>>>(w1);

    dim3 g((n + 127) / 128, 2);
    gemm_mma<<<g, 256, smemBytes>>>(z_p, z_o, b1, n);

    long totalE = 3L * E;                          // even
    long groups = (totalE + 1) / 2;                // 2 edges per 8-lane group
    int blocks = (int)((groups * 8 + 255) / 256);
    edge_all<<<blocks, 256>>>(e1, e2, e3, w2, b2, out, E);
}

// round 9
// speedup vs baseline: 3.5716x; 1.2389x over previous
#include <cuda_runtime.h>
#include <cuda_fp16.h>
#include <cstdint>

#define NMAX 100000
#define HH   128
#define KS2  136          // padded row stride (half elems) for K=128 tiles

// Per-node projections (fp16). [node][256]: cols 0..127 = z@W1a (left/src),
// cols 128..255 = z@W1b + b1 (right/dst, bias folded).
__device__ __half g_P[(size_t)NMAX * 256];
__device__ __half g_O[(size_t)NMAX * 256];

// Pre-built B' image: [n(256 output cols)][KS2] fp16 (w1 transposed, fp16).
__device__ __align__(16) __half g_Bimg[256 * KS2];

// ---------------- helpers ----------------
__device__ __forceinline__ uint32_t smem_u32(const void* p) {
    uint32_t a;
    asm("{ .reg .u64 t; cvta.to.shared.u64 t, %1; cvt.u32.u64 %0, t; }"
        : "=r"(a) : "l"(p));
    return a;
}

__device__ __forceinline__ void ldsm_x4(uint32_t* r, uint32_t addr) {
    asm volatile("ldmatrix.sync.aligned.m8n8.x4.shared.b16 {%0,%1,%2,%3}, [%4];\n"
                 : "=r"(r[0]), "=r"(r[1]), "=r"(r[2]), "=r"(r[3]) : "r"(addr));
}

__device__ __forceinline__ void mma_f16(float* c, const uint32_t* a,
                                        uint32_t b0, uint32_t b1) {
    asm volatile(
        "mma.sync.aligned.m16n8k16.row.col.f32.f16.f16.f32 "
        "{%0,%1,%2,%3}, {%4,%5,%6,%7}, {%8,%9}, {%0,%1,%2,%3};\n"
        : "+f"(c[0]), "+f"(c[1]), "+f"(c[2]), "+f"(c[3])
        : "r"(a[0]), "r"(a[1]), "r"(a[2]), "r"(a[3]), "r"(b0), "r"(b1));
}

// 32B gather load, pinned in L2 (evict_last requires v8.b32 on this ptxas)
__device__ __forceinline__ void ldg_el8(const void* p, uint4& a, uint4& b) {
    asm volatile(
        "ld.global.nc.L2::evict_last.v8.b32 {%0,%1,%2,%3,%4,%5,%6,%7}, [%8];"
        : "=r"(a.x), "=r"(a.y), "=r"(a.z), "=r"(a.w),
          "=r"(b.x), "=r"(b.y), "=r"(b.z), "=r"(b.w)
        : "l"(p));
}

// ---------------- prep: build B' image once ----------------
__global__ void prep_B(const float* __restrict__ w1) {
    int i = blockIdx.x * blockDim.x + threadIdx.x;   // over 256*128
    if (i >= 256 * 128) return;
    int nn = i >> 7;            // output col 0..255
    int k = i & 127;
    int cb = nn >> 7;
    int nloc = nn & 127;
    g_Bimg[(size_t)nn * KS2 + k] = __float2half_rn(w1[(cb * 128 + k) * 128 + nloc]);
}

// ---------------- GEMM: C[128 rows][256 cols] per CTA via mma.sync ----------------
// grid = (ceil(n/128), 2 matrices), 256 threads. K=128 fp16 direct.
// B streamed in 4 chunks of 64 cols, double-buffered cp.async.
__global__ __launch_bounds__(256, 2)
void gemm_mma(const float* __restrict__ Zp, const float* __restrict__ Zo,
              const float* __restrict__ b1, int n) {
    extern __shared__ __half smem[];
    __half* As = smem;                       // [128][KS2]
    __half* Bs[2] = { smem + 128 * KS2,      // [64][KS2] buf0
                      smem + 192 * KS2 };    // [64][KS2] buf1

    const int tid = threadIdx.x;
    const int lane = tid & 31;
    const int wid = tid >> 5;
    const int wm = wid & 3;          // 4 warps over M (32 rows)
    const int wn = wid >> 2;         // 2 warps over 32-col halves of chunk

    const float* A = blockIdx.y ? Zo : Zp;
    __half* C = blockIdx.y ? g_O : g_P;
    const long rowBase = (long)blockIdx.x * 128;

    auto cpchunk = [&](int c, __half* dst) {
        const __half* src = g_Bimg + (size_t)c * 64 * KS2;
        uint32_t d = smem_u32(dst);
        for (int i = tid; i < 64 * KS2 / 8; i += 256)
            asm volatile("cp.async.cg.shared.global [%0], [%1], 16;\n"
                         :: "r"(d + i * 16), "l"(src + i * 8) : "memory");
    };

    cpchunk(0, Bs[0]);
    asm volatile("cp.async.commit_group;\n" ::: "memory");
    cpchunk(1, Bs[1]);
    asm volatile("cp.async.commit_group;\n" ::: "memory");

    // ---- load A tile (128 rows x 128 fp32) -> fp16 ----
    {
        int row = tid >> 1;
        int half = tid & 1;                          // cols [half*64, half*64+64)
        long grow = rowBase + row;
        const float* ap = A + grow * HH + half * 64;
        __half* as = As + row * KS2 + half * 64;
        #pragma unroll
        for (int j = 0; j < 16; j++) {
            float4 v = (grow < n) ? reinterpret_cast<const float4*>(ap)[j]
                                  : make_float4(0.f, 0.f, 0.f, 0.f);
            __half2 h0 = __floats2half2_rn(v.x, v.y);
            __half2 h1 = __floats2half2_rn(v.z, v.w);
            uint2 hh;
            hh.x = *reinterpret_cast<uint32_t*>(&h0);
            hh.y = *reinterpret_cast<uint32_t*>(&h1);
            *reinterpret_cast<uint2*>(as + j * 4) = hh;
        }
    }

    asm volatile("cp.async.wait_group 1;\n" ::: "memory");
    __syncthreads();

    const uint32_t sbA = smem_u32(As);
    const uint32_t sbB[2] = { smem_u32(Bs[0]), smem_u32(Bs[1]) };
    uint32_t a_base[2], b_off[2];
    #pragma unroll
    for (int tm = 0; tm < 2; tm++)
        a_base[tm] = sbA + ((wm * 32 + tm * 16 + (lane & 15)) * KS2
                            + (lane >> 4) * 8) * 2;
    #pragma unroll
    for (int np = 0; np < 2; np++)
        b_off[np] = ((wn * 32 + np * 16 + ((lane >> 4) << 3) + (lane & 7)) * KS2
                      + ((lane >> 3) & 1) * 8) * 2;

    for (int c = 0; c < 4; c++) {
        const uint32_t bb = sbB[c & 1];
        float acc[2][4][4];
        #pragma unroll
        for (int tm = 0; tm < 2; tm++)
            #pragma unroll
            for (int tn = 0; tn < 4; tn++)
                #pragma unroll
                for (int q = 0; q < 4; q++) acc[tm][tn][q] = 0.f;

        #pragma unroll 2
        for (int ks = 0; ks < 8; ks++) {
            uint32_t a[2][4], b[2][4];
            #pragma unroll
            for (int tm = 0; tm < 2; tm++) ldsm_x4(a[tm], a_base[tm] + ks * 32);
            #pragma unroll
            for (int np = 0; np < 2; np++) ldsm_x4(b[np], bb + b_off[np] + ks * 32);
            #pragma unroll
            for (int tm = 0; tm < 2; tm++)
                #pragma unroll
                for (int tn = 0; tn < 4; tn++)
                    mma_f16(acc[tm][tn], a[tm],
                            b[tn >> 1][(tn & 1) * 2], b[tn >> 1][(tn & 1) * 2 + 1]);
        }

        __syncthreads();   // everyone done reading this buffer
        if (c + 2 < 4) {
            cpchunk(c + 2, Bs[c & 1]);
            asm volatile("cp.async.commit_group;\n" ::: "memory");
        }

        // ---- epilogue: fp32 acc (+b1 on right half) -> fp16 C ----
        #pragma unroll
        for (int tm = 0; tm < 2; tm++) {
            long r0 = rowBase + wm * 32 + tm * 16 + (lane >> 2);
            long r1 = r0 + 8;
            int colBase = c * 64 + wn * 32 + (lane & 3) * 2;
            #pragma unroll
            for (int tn = 0; tn < 4; tn++) {
                int col = colBase + tn * 8;
                float bx = 0.f, by = 0.f;
                if (col >= 128) {                       // right half: fold b1
                    float2 bv = *reinterpret_cast<const float2*>(b1 + col - 128);
                    bx = bv.x; by = bv.y;
                }
                if (r0 < n) {
                    __half2 v = __floats2half2_rn(acc[tm][tn][0] + bx,
                                                  acc[tm][tn][1] + by);
                    *reinterpret_cast<__half2*>(C + r0 * 256 + col) = v;
                }
                if (r1 < n) {
                    __half2 v = __floats2half2_rn(acc[tm][tn][2] + bx,
                                                  acc[tm][tn][3] + by);
                    *reinterpret_cast<__half2*>(C + r1 * 256 + col) = v;
                }
            }
        }

        if (c == 2) {
            asm volatile("cp.async.wait_group 0;\n" ::: "memory");
        } else if (c < 2) {
            asm volatile("cp.async.wait_group 1;\n" ::: "memory");
        }
        __syncthreads();
    }
}

// ---------------- edge decode: 8 lanes per edge, 2 edges per lane-group ----------------
__global__ __launch_bounds__(256)
void edge_all(const int* __restrict__ e1, const int* __restrict__ e2,
              const int* __restrict__ e3,
              const float* __restrict__ w2, const float* __restrict__ b2,
              float* __restrict__ out, int E) {
    const int tid = threadIdx.x;
    const int l = tid & 7;
    long g = (((long)blockIdx.x << 8) + tid) >> 3;   // lane-group id
    long eA = 2 * g;
    long eB = eA + 1;
    const long TE = 3L * E;
    if (eA >= TE) return;                            // TE even -> eB valid too

    // resolve edge A
    int tA = (eA >= 2L * E) ? 2 : (eA >= (long)E ? 1 : 0);
    int lA = (int)(eA - (long)tA * E);
    const int* iA = (tA == 0) ? e1 : ((tA == 1) ? e2 : e3);
    const __half* XA = (tA == 0) ? g_P : g_O;
    const __half* YA = ((tA == 1) ? g_P : g_O) + 128;
    // resolve edge B
    int tB = (eB >= 2L * E) ? 2 : (eB >= (long)E ? 1 : 0);
    int lB = (int)(eB - (long)tB * E);
    const int* iB = (tB == 0) ? e1 : ((tB == 1) ? e2 : e3);
    const __half* XB = (tB == 0) ? g_P : g_O;
    const __half* YB = ((tB == 1) ? g_P : g_O) + 128;

    int sA = iA[lA], dA = iA[lA + E];
    int sB = iB[lB], dB = iB[lB + E];

    const __half* xrA = XA + (size_t)sA * 256 + l * 16;
    const __half* yrA = YA + (size_t)dA * 256 + l * 16;
    const __half* xrB = XB + (size_t)sB * 256 + l * 16;
    const __half* yrB = YB + (size_t)dB * 256 + l * 16;

    // 4 independent 32B gathers in flight
    uint4 xa0, xa1, ya0, ya1, xb0, xb1, yb0, yb1;
    ldg_el8(xrA, xa0, xa1);
    ldg_el8(yrA, ya0, ya1);
    ldg_el8(xrB, xb0, xb1);
    ldg_el8(yrB, yb0, yb1);

    float2 w2v[8];
    #pragma unroll
    for (int j = 0; j < 4; j++) {
        float4 wv = reinterpret_cast<const float4*>(w2 + l * 16)[j];
        w2v[2 * j]     = make_float2(wv.x, wv.y);
        w2v[2 * j + 1] = make_float2(wv.z, wv.w);
    }
    const __half2 z2 = __float2half2_rn(0.f);

    const __half2* hxA0 = reinterpret_cast<const __half2*>(&xa0);
    const __half2* hxA1 = reinterpret_cast<const __half2*>(&xa1);
    const __half2* hyA0 = reinterpret_cast<const __half2*>(&ya0);
    const __half2* hyA1 = reinterpret_cast<const __half2*>(&ya1);
    const __half2* hxB0 = reinterpret_cast<const __half2*>(&xb0);
    const __half2* hxB1 = reinterpret_cast<const __half2*>(&xb1);
    const __half2* hyB0 = reinterpret_cast<const __half2*>(&yb0);
    const __half2* hyB1 = reinterpret_cast<const __half2*>(&yb1);

    float sA0 = 0.f, sA1 = 0.f, sB0 = 0.f, sB1 = 0.f;
    #pragma unroll
    for (int p = 0; p < 8; p++) {
        __half2 xA = (p < 4) ? hxA0[p] : hxA1[p - 4];
        __half2 yA = (p < 4) ? hyA0[p] : hyA1[p - 4];
        __half2 xB = (p < 4) ? hxB0[p] : hxB1[p - 4];
        __half2 yB = (p < 4) ? hyB0[p] : hyB1[p - 4];
        float2 rA = __half22float2(__hmax2(__hadd2(xA, yA), z2));
        float2 rB = __half22float2(__hmax2(__hadd2(xB, yB), z2));
        sA0 = fmaf(rA.x, w2v[p].x, sA0);
        sA1 = fmaf(rA.y, w2v[p].y, sA1);
        sB0 = fmaf(rB.x, w2v[p].x, sB0);
        sB1 = fmaf(rB.y, w2v[p].y, sB1);
    }
    float sumA = sA0 + sA1;
    float sumB = sB0 + sB1;

    #pragma unroll
    for (int o = 4; o > 0; o >>= 1) {
        sumA += __shfl_xor_sync(0xffffffffu, sumA, o);
        sumB += __shfl_xor_sync(0xffffffffu, sumB, o);
    }

    float bias = __ldg(b2);
    if (l == 0) out[eA] = sumA + bias;
    if (l == 1) out[eB] = sumB + bias;
}

extern "C" void kernel_launch(void* const* d_in, const int* in_sizes, int n_in,
                              void* d_out, int out_size) {
    const float* z_p = (const float*)d_in[0];
    const float* z_o = (const float*)d_in[1];
    const int*   e1  = (const int*)d_in[2];   // ptnp:  pnode src, onode dst
    const int*   e2  = (const int*)d_in[3];   // nptp:  onode src, pnode dst
    const int*   e3  = (const int*)d_in[4];   // nptnp: onode src, onode dst
    const float* w1  = (const float*)d_in[5];
    const float* b1  = (const float*)d_in[6];
    const float* w2  = (const float*)d_in[7];
    const float* b2  = (const float*)d_in[8];
    float* out = (float*)d_out;

    const int n = in_sizes[0] / HH;       // 100000
    const int E = in_sizes[2] / 2;        // 500000
    (void)n_in; (void)out_size;

    const int smemBytes = (128 * KS2 + 2 * 64 * KS2) * 2;   // 69632 B
    cudaFuncSetAttribute(gemm_mma, cudaFuncAttributeMaxDynamicSharedMemorySize,
                         smemBytes);

    prep_B<<<(256 * 128 + 255) / 256, 256>>>(w1);

    dim3 g((n + 127) / 128, 2);
    gemm_mma<<<g, 256, smemBytes>>>(z_p, z_o, b1, n);

    long totalE = 3L * E;                          // even
    long groups = (totalE + 1) / 2;                // 2 edges per 8-lane group
    int blocks = (int)((groups * 8 + 255) / 256);
    edge_all<<<blocks, 256>>>(e1, e2, e3, w2, b2, out, E);
}